// round 4
// baseline (speedup 1.0000x reference)
#include <cuda_runtime.h>
#include <cuda_bf16.h>
#include <stdint.h>

#define BB 4
#define NN 2048
#define MM 8192
#define DD 128
#define SS 1024   // NUM_SEGMENTS
#define HB 8      // hist blocks per batch
#define ROWS_PER_BLK (MM / HB)   // 1024
#define NB 128    // persistent grid size (<=148 SMs -> all co-resident)
#define NWARP (NB * 8)           // 1024 warps total

// ---------------- scratch (static __device__, no allocation) ----------------
__device__ float g_seg_sum[BB * SS * DD];   // 2 MB
__device__ int   g_blkhist[BB * HB * SS];
__device__ int   g_cnt[BB * SS];
__device__ float g_inv[BB * SS];
__device__ int   g_off[BB * SS];
__device__ int   g_rows[BB * MM];

// grid barrier state (monotone generation; consistent across graph replays)
__device__ unsigned g_bar_count = 0;
__device__ unsigned g_bar_gen   = 0;

__device__ __forceinline__ void grid_barrier() {
    __syncthreads();
    if (threadIdx.x == 0) {
        unsigned gen = *((volatile unsigned*)&g_bar_gen);
        __threadfence();
        if (atomicAdd(&g_bar_count, 1u) == NB - 1u) {
            atomicExch(&g_bar_count, 0u);
            __threadfence();
            atomicAdd(&g_bar_gen, 1u);
        } else {
            while (*((volatile unsigned*)&g_bar_gen) == gen) { }
        }
        __threadfence();
    }
    __syncthreads();
}

__global__ __launch_bounds__(256) void k_fused(const int* __restrict__ idx_tgt,
                                               const int* __restrict__ idx_src,
                                               const float* __restrict__ src,
                                               float* __restrict__ out) {
    __shared__ int sh[SS];     // phase1: hist; phase2: cursors
    __shared__ int wsum[8];
    const int t    = threadIdx.x;
    const int lane = t & 31;
    const int w    = t >> 5;
    const int blk  = blockIdx.x;

    // ================= Phase 1: per-block private histogram (blocks 0..31) ==========
    if (blk < BB * HB) {
        const int b = blk >> 3;
        const int i = blk & 7;
        ((int4*)sh)[t] = make_int4(0, 0, 0, 0);
        __syncthreads();
        int4 a = ((const int4*)(idx_src + b * MM + i * ROWS_PER_BLK))[t];
        atomicAdd(&sh[a.x], 1); atomicAdd(&sh[a.y], 1);
        atomicAdd(&sh[a.z], 1); atomicAdd(&sh[a.w], 1);
        __syncthreads();
        ((int4*)(g_blkhist + (b * HB + i) * SS))[t] = ((int4*)sh)[t];
    }
    grid_barrier();

    // ================= Phase 2: scan + scatter (blocks 0..31) =======================
    if (blk < BB * HB) {
        const int b = blk >> 3;
        const int i = blk & 7;

        int4 tot = make_int4(0, 0, 0, 0);
        int4 pre = make_int4(0, 0, 0, 0);
        #pragma unroll
        for (int j = 0; j < HB; j++) {
            int4 h4 = ((const int4*)(g_blkhist + (b * HB + j) * SS))[t];
            tot.x += h4.x; tot.y += h4.y; tot.z += h4.z; tot.w += h4.w;
            if (j < i) { pre.x += h4.x; pre.y += h4.y; pre.z += h4.z; pre.w += h4.w; }
        }
        int l0 = tot.x, l1 = l0 + tot.y, l2 = l1 + tot.z, l3 = l2 + tot.w;

        int inc = l3;
        #pragma unroll
        for (int d = 1; d < 32; d <<= 1) {
            int up = __shfl_up_sync(0xffffffffu, inc, d);
            if (lane >= d) inc += up;
        }
        if (lane == 31) wsum[w] = inc;
        __syncthreads();
        if (w == 0) {
            int v = (lane < 8) ? wsum[lane] : 0;
            #pragma unroll
            for (int d = 1; d < 8; d <<= 1) {
                int up = __shfl_up_sync(0xffffffffu, v, d);
                if (lane >= d) v += up;
            }
            if (lane < 8) wsum[lane] = v;
        }
        __syncthreads();
        int excl = inc - l3 + (w > 0 ? wsum[w - 1] : 0);

        int o0 = excl, o1 = excl + l0, o2 = excl + l1, o3 = excl + l2;

        if (i == 0) {
            int s = 4 * t;
            g_cnt[b * SS + s + 0] = tot.x;  g_off[b * SS + s + 0] = o0;
            g_cnt[b * SS + s + 1] = tot.y;  g_off[b * SS + s + 1] = o1;
            g_cnt[b * SS + s + 2] = tot.z;  g_off[b * SS + s + 2] = o2;
            g_cnt[b * SS + s + 3] = tot.w;  g_off[b * SS + s + 3] = o3;
            g_inv[b * SS + s + 0] = 1.0f / ((float)tot.x + 1e-10f);
            g_inv[b * SS + s + 1] = 1.0f / ((float)tot.y + 1e-10f);
            g_inv[b * SS + s + 2] = 1.0f / ((float)tot.z + 1e-10f);
            g_inv[b * SS + s + 3] = 1.0f / ((float)tot.w + 1e-10f);
        }

        sh[4 * t + 0] = o0 + pre.x;
        sh[4 * t + 1] = o1 + pre.y;
        sh[4 * t + 2] = o2 + pre.z;
        sh[4 * t + 3] = o3 + pre.w;
        __syncthreads();

        int4 a = ((const int4*)(idx_src + b * MM + i * ROWS_PER_BLK))[t];
        int m = i * ROWS_PER_BLK + 4 * t;
        int* rows = g_rows + b * MM;
        int q;
        q = atomicAdd(&sh[a.x], 1); rows[q] = m + 0;
        q = atomicAdd(&sh[a.y], 1); rows[q] = m + 1;
        q = atomicAdd(&sh[a.z], 1); rows[q] = m + 2;
        q = atomicAdd(&sh[a.w], 1); rows[q] = m + 3;
    }
    grid_barrier();

    // ================= Phase 3: segment sums (all blocks, 4 segs/warp) ==============
    {
        int gwarp = blk * 8 + w;
        for (int seg = gwarp; seg < BB * SS; seg += NWARP) {
            int b = seg >> 10;
            int cnt = g_cnt[seg];
            int off = g_off[seg];
            const int* rows = g_rows + b * MM + off;
            const float* base = src + (size_t)b * MM * DD;

            float4 acc0 = {0,0,0,0}, acc1 = {0,0,0,0}, acc2 = {0,0,0,0}, acc3 = {0,0,0,0};
            int r = 0;
            for (; r + 4 <= cnt; r += 4) {
                int m0 = rows[r], m1 = rows[r+1], m2 = rows[r+2], m3 = rows[r+3];
                float4 v0 = ((const float4*)(base + (size_t)m0 * DD))[lane];
                float4 v1 = ((const float4*)(base + (size_t)m1 * DD))[lane];
                float4 v2 = ((const float4*)(base + (size_t)m2 * DD))[lane];
                float4 v3 = ((const float4*)(base + (size_t)m3 * DD))[lane];
                acc0.x += v0.x; acc0.y += v0.y; acc0.z += v0.z; acc0.w += v0.w;
                acc1.x += v1.x; acc1.y += v1.y; acc1.z += v1.z; acc1.w += v1.w;
                acc2.x += v2.x; acc2.y += v2.y; acc2.z += v2.z; acc2.w += v2.w;
                acc3.x += v3.x; acc3.y += v3.y; acc3.z += v3.z; acc3.w += v3.w;
            }
            for (; r < cnt; r++) {
                int m = rows[r];
                float4 v = ((const float4*)(base + (size_t)m * DD))[lane];
                acc0.x += v.x; acc0.y += v.y; acc0.z += v.z; acc0.w += v.w;
            }
            acc0.x += acc1.x + acc2.x + acc3.x;
            acc0.y += acc1.y + acc2.y + acc3.y;
            acc0.z += acc1.z + acc2.z + acc3.z;
            acc0.w += acc1.w + acc2.w + acc3.w;
            ((float4*)(g_seg_sum + (size_t)seg * DD))[lane] = acc0;
        }
    }
    grid_barrier();

    // ================= Phase 4: gather, 8 targets/warp with ILP-8 ===================
    {
        int gwarp = blk * 8 + w;
        int tw = gwarp * 8;                       // first target (8 per warp; same batch)
        int b = tw >> 11;                          // tw / NN
        int smine = idx_tgt[tw + (lane & 7)];      // 8 distinct addrs, broadcast in warp
        int slotmine = (b << 10) + smine;
        float invmine = g_inv[slotmine];
        #pragma unroll
        for (int k = 0; k < 8; k++) {
            int slot  = __shfl_sync(0xffffffffu, slotmine, k);
            float inv = __shfl_sync(0xffffffffu, invmine, k);
            float4 v = ((const float4*)(g_seg_sum + (size_t)slot * DD))[lane];
            v.x *= inv; v.y *= inv; v.z *= inv; v.w *= inv;
            ((float4*)(out + (size_t)(tw + k) * DD))[lane] = v;
        }
    }
}

// ---------------- launch ----------------
extern "C" void kernel_launch(void* const* d_in, const int* in_sizes, int n_in,
                              void* d_out, int out_size) {
    const int*   idx_tgt = (const int*)d_in[0];
    const int*   idx_src = (const int*)d_in[1];
    const float* src     = (const float*)d_in[2];
    float*       out     = (float*)d_out;

    k_fused<<<NB, 256>>>(idx_tgt, idx_src, src, out);
}

// round 5
// speedup vs baseline: 1.3772x; 1.3772x over previous
#include <cuda_runtime.h>
#include <cuda_bf16.h>
#include <stdint.h>

#define BB 4
#define NN 2048
#define MM 8192
#define DD 128
#define SS 1024   // NUM_SEGMENTS
#define HB 8      // hist blocks per batch
#define ROWS_PER_BLK (MM / HB)   // 1024

// ---------------- scratch (static __device__, no allocation) ----------------
__device__ float g_seg_sum[BB * SS * DD];   // 2 MB
__device__ int   g_blkhist[BB * HB * SS];
__device__ int   g_cnt[BB * SS];
__device__ float g_inv[BB * SS];
__device__ int   g_off[BB * SS];
__device__ int   g_rows[BB * MM];

// ---------------- 1) per-block private histogram (no global atomics) ----------------
__global__ __launch_bounds__(256) void k_blockhist(const int* __restrict__ idx_src) {
    __shared__ int h[SS];
    const int b = blockIdx.x >> 3;
    const int i = blockIdx.x & 7;
    const int t = threadIdx.x;

    ((int4*)h)[t] = make_int4(0, 0, 0, 0);
    __syncthreads();

    int4 a = ((const int4*)(idx_src + b * MM + i * ROWS_PER_BLK))[t];
    atomicAdd(&h[a.x], 1); atomicAdd(&h[a.y], 1);
    atomicAdd(&h[a.z], 1); atomicAdd(&h[a.w], 1);
    __syncthreads();

    ((int4*)(g_blkhist + (b * HB + i) * SS))[t] = ((int4*)h)[t];
}

// ---------------- 2) scan + scatter (shared cursors, exact global offsets) ----------------
__global__ __launch_bounds__(256) void k_scatter(const int* __restrict__ idx_src) {
    __shared__ int curs[SS];
    __shared__ int wsum[8];
    const int b = blockIdx.x >> 3;
    const int i = blockIdx.x & 7;
    const int t = threadIdx.x;
    const int lane = t & 31;
    const int w = t >> 5;

    int4 tot = make_int4(0, 0, 0, 0);
    int4 pre = make_int4(0, 0, 0, 0);
    #pragma unroll
    for (int j = 0; j < HB; j++) {
        int4 h4 = ((const int4*)(g_blkhist + (b * HB + j) * SS))[t];
        tot.x += h4.x; tot.y += h4.y; tot.z += h4.z; tot.w += h4.w;
        if (j < i) { pre.x += h4.x; pre.y += h4.y; pre.z += h4.z; pre.w += h4.w; }
    }
    int l0 = tot.x, l1 = l0 + tot.y, l2 = l1 + tot.z, l3 = l2 + tot.w;

    int inc = l3;
    #pragma unroll
    for (int d = 1; d < 32; d <<= 1) {
        int up = __shfl_up_sync(0xffffffffu, inc, d);
        if (lane >= d) inc += up;
    }
    if (lane == 31) wsum[w] = inc;
    __syncthreads();
    if (w == 0) {
        int v = (lane < 8) ? wsum[lane] : 0;
        #pragma unroll
        for (int d = 1; d < 8; d <<= 1) {
            int up = __shfl_up_sync(0xffffffffu, v, d);
            if (lane >= d) v += up;
        }
        if (lane < 8) wsum[lane] = v;
    }
    __syncthreads();
    int excl = inc - l3 + (w > 0 ? wsum[w - 1] : 0);

    int o0 = excl, o1 = excl + l0, o2 = excl + l1, o3 = excl + l2;

    if (i == 0) {
        int s = 4 * t;
        g_cnt[b * SS + s + 0] = tot.x;  g_off[b * SS + s + 0] = o0;
        g_cnt[b * SS + s + 1] = tot.y;  g_off[b * SS + s + 1] = o1;
        g_cnt[b * SS + s + 2] = tot.z;  g_off[b * SS + s + 2] = o2;
        g_cnt[b * SS + s + 3] = tot.w;  g_off[b * SS + s + 3] = o3;
        g_inv[b * SS + s + 0] = 1.0f / ((float)tot.x + 1e-10f);
        g_inv[b * SS + s + 1] = 1.0f / ((float)tot.y + 1e-10f);
        g_inv[b * SS + s + 2] = 1.0f / ((float)tot.z + 1e-10f);
        g_inv[b * SS + s + 3] = 1.0f / ((float)tot.w + 1e-10f);
    }

    curs[4 * t + 0] = o0 + pre.x;
    curs[4 * t + 1] = o1 + pre.y;
    curs[4 * t + 2] = o2 + pre.z;
    curs[4 * t + 3] = o3 + pre.w;
    __syncthreads();

    int4 a = ((const int4*)(idx_src + b * MM + i * ROWS_PER_BLK))[t];
    int m = i * ROWS_PER_BLK + 4 * t;
    int* rows = g_rows + b * MM;
    int q;
    q = atomicAdd(&curs[a.x], 1); rows[q] = m + 0;
    q = atomicAdd(&curs[a.y], 1); rows[q] = m + 1;
    q = atomicAdd(&curs[a.z], 1); rows[q] = m + 2;
    q = atomicAdd(&curs[a.w], 1); rows[q] = m + 3;
}

// ---------------- 3) per-(b,segment) sum: one warp per segment, MLP=4 ----------------
__global__ void k_segsum(const float* __restrict__ src) {
    int warp = (blockIdx.x * blockDim.x + threadIdx.x) >> 5;
    int lane = threadIdx.x & 31;
    if (warp >= BB * SS) return;
    int b = warp >> 10;
    int cnt = g_cnt[warp];
    int off = g_off[warp];
    const int* rows = g_rows + b * MM + off;
    const float* base = src + (size_t)b * MM * DD;

    float4 acc0 = {0,0,0,0}, acc1 = {0,0,0,0}, acc2 = {0,0,0,0}, acc3 = {0,0,0,0};
    int r = 0;
    for (; r + 4 <= cnt; r += 4) {
        int m0 = rows[r], m1 = rows[r+1], m2 = rows[r+2], m3 = rows[r+3];
        float4 v0 = ((const float4*)(base + (size_t)m0 * DD))[lane];
        float4 v1 = ((const float4*)(base + (size_t)m1 * DD))[lane];
        float4 v2 = ((const float4*)(base + (size_t)m2 * DD))[lane];
        float4 v3 = ((const float4*)(base + (size_t)m3 * DD))[lane];
        acc0.x += v0.x; acc0.y += v0.y; acc0.z += v0.z; acc0.w += v0.w;
        acc1.x += v1.x; acc1.y += v1.y; acc1.z += v1.z; acc1.w += v1.w;
        acc2.x += v2.x; acc2.y += v2.y; acc2.z += v2.z; acc2.w += v2.w;
        acc3.x += v3.x; acc3.y += v3.y; acc3.z += v3.z; acc3.w += v3.w;
    }
    for (; r < cnt; r++) {
        int m = rows[r];
        float4 v = ((const float4*)(base + (size_t)m * DD))[lane];
        acc0.x += v.x; acc0.y += v.y; acc0.z += v.z; acc0.w += v.w;
    }
    acc0.x += acc1.x + acc2.x + acc3.x;
    acc0.y += acc1.y + acc2.y + acc3.y;
    acc0.z += acc1.z + acc2.z + acc3.z;
    acc0.w += acc1.w + acc2.w + acc3.w;
    ((float4*)(g_seg_sum + (size_t)warp * DD))[lane] = acc0;
}

// ---------------- 4) gather: 8 targets per warp, ILP-8 ----------------
__global__ __launch_bounds__(256) void k_gather(const int* __restrict__ idx_tgt,
                                                float* __restrict__ out) {
    int gwarp = (blockIdx.x * blockDim.x + threadIdx.x) >> 5;  // 0..BB*NN/8-1
    int lane  = threadIdx.x & 31;
    if (gwarp >= BB * NN / 8) return;
    int tw = gwarp * 8;                        // 8 consecutive targets, same batch
    int b  = tw >> 11;                         // tw / NN
    int smine    = idx_tgt[tw + (lane & 7)];   // 8 distinct idx, warp-broadcast
    int slotmine = (b << 10) + smine;
    float invmine = g_inv[slotmine];
    #pragma unroll
    for (int k = 0; k < 8; k++) {
        int slot  = __shfl_sync(0xffffffffu, slotmine, k);
        float inv = __shfl_sync(0xffffffffu, invmine, k);
        float4 v = ((const float4*)(g_seg_sum + (size_t)slot * DD))[lane];
        v.x *= inv; v.y *= inv; v.z *= inv; v.w *= inv;
        ((float4*)(out + (size_t)(tw + k) * DD))[lane] = v;
    }
}

// ---------------- launch ----------------
extern "C" void kernel_launch(void* const* d_in, const int* in_sizes, int n_in,
                              void* d_out, int out_size) {
    const int*   idx_tgt = (const int*)d_in[0];
    const int*   idx_src = (const int*)d_in[1];
    const float* src     = (const float*)d_in[2];
    float*       out     = (float*)d_out;

    k_blockhist<<<BB * HB, 256>>>(idx_src);
    k_scatter  <<<BB * HB, 256>>>(idx_src);
    k_segsum   <<<(BB * SS * 32 + 255) / 256, 256>>>(src);
    k_gather   <<<(BB * NN / 8 * 32 + 255) / 256, 256>>>(idx_tgt, out);
}

// round 6
// speedup vs baseline: 1.7451x; 1.2672x over previous
#include <cuda_runtime.h>
#include <cuda_bf16.h>
#include <stdint.h>

#define BB 4
#define NN 2048
#define MM 8192
#define DD 128
#define SS 1024    // NUM_SEGMENTS
#define HB 8       // hist blocks per batch (source)
#define HBT 2      // hist blocks per batch (target)
#define SRC_ROWS_PER_BLK (MM / HB)    // 1024
#define TGT_ROWS_PER_BLK (NN / HBT)   // 1024
#define NSRC_BLKS (BB * HB)           // 32
#define NTGT_BLKS (BB * HBT)          // 8

// ---------------- scratch (static __device__, no allocation) ----------------
__device__ int g_blkhist_s[BB * HB * SS];
__device__ int g_blkhist_t[BB * HBT * SS];
__device__ int g_cnt_s[BB * SS];
__device__ int g_off_s[BB * SS];
__device__ int g_cnt_t[BB * SS];
__device__ int g_off_t[BB * SS];
__device__ int g_rows_s[BB * MM];   // source rows grouped by segment
__device__ int g_rows_t[BB * NN];   // target rows grouped by segment

// ---------------- 1) per-block private histograms (src blocks 0..31, tgt 32..39) ----
__global__ __launch_bounds__(256) void k_hist(const int* __restrict__ idx_src,
                                              const int* __restrict__ idx_tgt) {
    __shared__ int h[SS];
    const int t = threadIdx.x;
    ((int4*)h)[t] = make_int4(0, 0, 0, 0);
    __syncthreads();

    const int* in;
    int* outh;
    if (blockIdx.x < NSRC_BLKS) {
        int b = blockIdx.x >> 3, i = blockIdx.x & 7;
        in   = idx_src + b * MM + i * SRC_ROWS_PER_BLK;
        outh = g_blkhist_s + (b * HB + i) * SS;
    } else {
        int u = blockIdx.x - NSRC_BLKS;
        int b = u >> 1, i = u & 1;
        in   = idx_tgt + b * NN + i * TGT_ROWS_PER_BLK;
        outh = g_blkhist_t + (b * HBT + i) * SS;
    }

    int4 a = ((const int4*)in)[t];
    atomicAdd(&h[a.x], 1); atomicAdd(&h[a.y], 1);
    atomicAdd(&h[a.z], 1); atomicAdd(&h[a.w], 1);
    __syncthreads();
    ((int4*)outh)[t] = ((int4*)h)[t];
}

// ---------------- 2) scan + scatter (both sorts; shared cursors) ----------------
__global__ __launch_bounds__(256) void k_scatter(const int* __restrict__ idx_src,
                                                 const int* __restrict__ idx_tgt) {
    __shared__ int curs[SS];
    __shared__ int wsum[8];
    const int t = threadIdx.x;
    const int lane = t & 31;
    const int w = t >> 5;

    int b, i, nblk;
    const int* hist;
    const int* in;
    int *rows, *cnt_out, *off_out;
    if (blockIdx.x < NSRC_BLKS) {
        b = blockIdx.x >> 3; i = blockIdx.x & 7; nblk = HB;
        hist = g_blkhist_s + b * HB * SS;
        in   = idx_src + b * MM + i * SRC_ROWS_PER_BLK;
        rows = g_rows_s + b * MM;
        cnt_out = g_cnt_s + b * SS; off_out = g_off_s + b * SS;
    } else {
        int u = blockIdx.x - NSRC_BLKS;
        b = u >> 1; i = u & 1; nblk = HBT;
        hist = g_blkhist_t + b * HBT * SS;
        in   = idx_tgt + b * NN + i * TGT_ROWS_PER_BLK;
        rows = g_rows_t + b * NN;
        cnt_out = g_cnt_t + b * SS; off_out = g_off_t + b * SS;
    }

    int4 tot = make_int4(0, 0, 0, 0);
    int4 pre = make_int4(0, 0, 0, 0);
    for (int j = 0; j < nblk; j++) {
        int4 h4 = ((const int4*)(hist + j * SS))[t];
        tot.x += h4.x; tot.y += h4.y; tot.z += h4.z; tot.w += h4.w;
        if (j < i) { pre.x += h4.x; pre.y += h4.y; pre.z += h4.z; pre.w += h4.w; }
    }
    int l0 = tot.x, l1 = l0 + tot.y, l2 = l1 + tot.z, l3 = l2 + tot.w;

    int inc = l3;
    #pragma unroll
    for (int d = 1; d < 32; d <<= 1) {
        int up = __shfl_up_sync(0xffffffffu, inc, d);
        if (lane >= d) inc += up;
    }
    if (lane == 31) wsum[w] = inc;
    __syncthreads();
    if (w == 0) {
        int v = (lane < 8) ? wsum[lane] : 0;
        #pragma unroll
        for (int d = 1; d < 8; d <<= 1) {
            int up = __shfl_up_sync(0xffffffffu, v, d);
            if (lane >= d) v += up;
        }
        if (lane < 8) wsum[lane] = v;
    }
    __syncthreads();
    int excl = inc - l3 + (w > 0 ? wsum[w - 1] : 0);

    int o0 = excl, o1 = excl + l0, o2 = excl + l1, o3 = excl + l2;

    if (i == 0) {
        int s = 4 * t;
        cnt_out[s + 0] = tot.x;  off_out[s + 0] = o0;
        cnt_out[s + 1] = tot.y;  off_out[s + 1] = o1;
        cnt_out[s + 2] = tot.z;  off_out[s + 2] = o2;
        cnt_out[s + 3] = tot.w;  off_out[s + 3] = o3;
    }

    curs[4 * t + 0] = o0 + pre.x;
    curs[4 * t + 1] = o1 + pre.y;
    curs[4 * t + 2] = o2 + pre.z;
    curs[4 * t + 3] = o3 + pre.w;
    __syncthreads();

    int4 a = ((const int4*)in)[t];
    int m = i * 1024 + 4 * t;   // both SRC_ROWS_PER_BLK and TGT_ROWS_PER_BLK are 1024
    int q;
    q = atomicAdd(&curs[a.x], 1); rows[q] = m + 0;
    q = atomicAdd(&curs[a.y], 1); rows[q] = m + 1;
    q = atomicAdd(&curs[a.z], 1); rows[q] = m + 2;
    q = atomicAdd(&curs[a.w], 1); rows[q] = m + 3;
}

// ---------------- 3) segsum + direct write to target rows ----------------
__global__ __launch_bounds__(128) void k_segsum_write(const float* __restrict__ src,
                                                      float* __restrict__ out) {
    int seg  = (blockIdx.x * blockDim.x + threadIdx.x) >> 5;  // 0..BB*SS-1
    int lane = threadIdx.x & 31;
    if (seg >= BB * SS) return;
    int b = seg >> 10;

    int tcnt = g_cnt_t[seg];
    if (tcnt == 0) return;               // no targets in this segment
    int toff = g_off_t[seg];
    int cnt  = g_cnt_s[seg];
    int off  = g_off_s[seg];

    const int* rows = g_rows_s + b * MM + off;
    const float* base = src + (size_t)b * MM * DD;

    float4 acc0 = {0,0,0,0}, acc1 = {0,0,0,0}, acc2 = {0,0,0,0}, acc3 = {0,0,0,0};
    int r = 0;
    for (; r + 4 <= cnt; r += 4) {
        int m0 = rows[r], m1 = rows[r+1], m2 = rows[r+2], m3 = rows[r+3];
        float4 v0 = ((const float4*)(base + (size_t)m0 * DD))[lane];
        float4 v1 = ((const float4*)(base + (size_t)m1 * DD))[lane];
        float4 v2 = ((const float4*)(base + (size_t)m2 * DD))[lane];
        float4 v3 = ((const float4*)(base + (size_t)m3 * DD))[lane];
        acc0.x += v0.x; acc0.y += v0.y; acc0.z += v0.z; acc0.w += v0.w;
        acc1.x += v1.x; acc1.y += v1.y; acc1.z += v1.z; acc1.w += v1.w;
        acc2.x += v2.x; acc2.y += v2.y; acc2.z += v2.z; acc2.w += v2.w;
        acc3.x += v3.x; acc3.y += v3.y; acc3.z += v3.z; acc3.w += v3.w;
    }
    for (; r < cnt; r++) {
        int m = rows[r];
        float4 v = ((const float4*)(base + (size_t)m * DD))[lane];
        acc0.x += v.x; acc0.y += v.y; acc0.z += v.z; acc0.w += v.w;
    }
    float inv = 1.0f / ((float)cnt + 1e-10f);
    float4 res;
    res.x = (acc0.x + acc1.x + acc2.x + acc3.x) * inv;
    res.y = (acc0.y + acc1.y + acc2.y + acc3.y) * inv;
    res.z = (acc0.z + acc1.z + acc2.z + acc3.z) * inv;
    res.w = (acc0.w + acc1.w + acc2.w + acc3.w) * inv;

    const int* trows = g_rows_t + b * NN + toff;
    float* outb = out + (size_t)b * NN * DD;
    for (int j = 0; j < tcnt; j++) {
        int n = trows[j];                                 // broadcast load
        ((float4*)(outb + (size_t)n * DD))[lane] = res;   // coalesced 512B store
    }
}

// ---------------- launch ----------------
extern "C" void kernel_launch(void* const* d_in, const int* in_sizes, int n_in,
                              void* d_out, int out_size) {
    const int*   idx_tgt = (const int*)d_in[0];
    const int*   idx_src = (const int*)d_in[1];
    const float* src     = (const float*)d_in[2];
    float*       out     = (float*)d_out;

    k_hist        <<<NSRC_BLKS + NTGT_BLKS, 256>>>(idx_src, idx_tgt);
    k_scatter     <<<NSRC_BLKS + NTGT_BLKS, 256>>>(idx_src, idx_tgt);
    k_segsum_write<<<(BB * SS * 32 + 127) / 128, 128>>>(src, out);
}